// round 13
// baseline (speedup 1.0000x reference)
#include <cuda_runtime.h>
#include <cstdint>

#define CIN 3
#define COUT 16
#define HH 32
#define WW 32
#define OH 30
#define OW 30

typedef unsigned long long u64;

// ---- f32x2 packed-math helpers (SASS FFMA2 via PTX only) ----
__device__ __forceinline__ u64 pk2(float a, float b) {
    u64 r; asm("mov.b64 %0, {%1, %2};" : "=l"(r) : "f"(a), "f"(b)); return r;
}
__device__ __forceinline__ u64 dup2(float a) {
    u64 r; asm("mov.b64 %0, {%1, %1};" : "=l"(r) : "f"(a)); return r;
}
__device__ __forceinline__ u64 fma2(u64 a, u64 b, u64 c) {
    u64 d; asm("fma.rn.f32x2 %0, %1, %2, %3;" : "=l"(d) : "l"(a), "l"(b), "l"(c)); return d;
}
__device__ __forceinline__ void upk2(u64 v, float& a, float& b) {
    asm("mov.b64 {%0, %1}, %2;" : "=f"(a), "=f"(b) : "l"(v));
}
// activation: relu(v)*min(v+3,6)/6 == max(v,0)*min(v/6+0.5, 1); t precomputed packed
__device__ __forceinline__ float hswish_relu(float v, float t) {
    return fmaxf(v, 0.0f) * fminf(t, 1.0f);
}

// Direct conv v7 — column-QUAD packing. One block = one image, 128 threads.
// Lane -> channel ch = warp*4 + (lane>>3), column group k = lane&7 (cols
// 4k..4k+3, two f32x2 accumulators). Per ci per input row: ONE LDS.128 + ONE
// LDS.64 deliver x[4k..4k+5]; q01/q23/q45 are direct FFMA2 operands, only the
// two middle pairs {x1,x2},{x3,x4} need packs. 18 FFMA2 per (ci,row) per lane
// -> fma pipe (108 cyc/warp-row) strictly exceeds issue (~104 slots): first
// genuinely fma-bound variant. All 32 lanes active (k=7 masks cols 30,31).
__global__ void __launch_bounds__(128, 4) conv3x3_hswish_kernel(
    const float* __restrict__ x,
    const float* __restrict__ wgt,
    const float* __restrict__ bias,
    float* __restrict__ out)
{
    __shared__ __align__(16) float s_in[CIN * HH * WW + 4];   // +4 pad: k=7 over-read

    const int n   = blockIdx.x;
    const int tid = threadIdx.x;

    {   // coalesced image load: 768 float4 / 128 threads = 6 each
        const float4* src = reinterpret_cast<const float4*>(x + (size_t)n * (CIN * HH * WW));
        float4* dst = reinterpret_cast<float4*>(s_in);
        #pragma unroll
        for (int i = 0; i < 6; i++) dst[tid + i * 128] = src[tid + i * 128];
    }
    __syncthreads();

    const int warp = tid >> 5;
    const int lane = tid & 31;
    const int ch   = warp * 4 + (lane >> 3);   // this lane's output channel
    const int k    = lane & 7;                 // column group: cols 4k..4k+3

    // per-lane duplicated weights {w,w} and bias
    u64 wd[27];
    #pragma unroll
    for (int t = 0; t < 27; t++) wd[t] = dup2(wgt[ch * 27 + t]);
    const u64 bd    = dup2(bias[ch]);
    const u64 sixth = dup2(1.0f / 6.0f);
    const u64 halfc = dup2(0.5f);

    const float* base = s_in + 4 * k;          // [ci*1024 + row*32 + 4k]
    float* outp = out + ((size_t)n * COUT + ch) * (OH * OW) + 4 * k;

    // double-buffered row window: per ci {q01, q23, q45} (u64 each)
    u64 qa[9], qb[9];
    u64 accP[3], accQ[3];   // accP: cols 4k,4k+1; accQ: cols 4k+2,4k+3

    #pragma unroll
    for (int ci = 0; ci < CIN; ci++) {         // preload input row 0
        qa[ci * 3 + 0] = *reinterpret_cast<const u64*>(base + ci * 1024 + 0);
        qa[ci * 3 + 1] = *reinterpret_cast<const u64*>(base + ci * 1024 + 2);
        qa[ci * 3 + 2] = *reinterpret_cast<const u64*>(base + ci * 1024 + 4);
    }

    #pragma unroll
    for (int r = 0; r < 32; r++) {
        // prefetch input row r+1 into the other buffer (full-row distance)
        if (r < 31) {
            #pragma unroll
            for (int ci = 0; ci < CIN; ci++) {
                const float* rp = base + ci * 1024 + (r + 1) * 32;
                const u64 v0 = *reinterpret_cast<const u64*>(rp + 0);
                const u64 v1 = *reinterpret_cast<const u64*>(rp + 2);
                const u64 v2 = *reinterpret_cast<const u64*>(rp + 4);
                if (r & 1) { qa[ci * 3 + 0] = v0; qa[ci * 3 + 1] = v1; qa[ci * 3 + 2] = v2; }
                else       { qb[ci * 3 + 0] = v0; qb[ci * 3 + 1] = v1; qb[ci * 3 + 2] = v2; }
            }
        }

        if (r <= 29) { accP[r % 3] = bd; accQ[r % 3] = bd; }

        #pragma unroll
        for (int ci = 0; ci < CIN; ci++) {
            const u64 q01 = (r & 1) ? qb[ci * 3 + 0] : qa[ci * 3 + 0];
            const u64 q23 = (r & 1) ? qb[ci * 3 + 1] : qa[ci * 3 + 1];
            const u64 q45 = (r & 1) ? qb[ci * 3 + 2] : qa[ci * 3 + 2];
            // middle pairs {x1,x2} and {x3,x4}
            float x0, x1, x2, x3, x4, x5;
            upk2(q01, x0, x1);
            upk2(q23, x2, x3);
            upk2(q45, x4, x5);
            const u64 pm12 = pk2(x1, x2);
            const u64 pm34 = pk2(x3, x4);

            const int wb = ci * 9;
            if (r >= 2) {                        // ky = 2 -> output row r-2
                const int d = (r - 2) % 3;
                accP[d] = fma2(q01, wd[wb + 6], accP[d]);
                accP[d] = fma2(pm12, wd[wb + 7], accP[d]);
                accP[d] = fma2(q23, wd[wb + 8], accP[d]);
                accQ[d] = fma2(q23, wd[wb + 6], accQ[d]);
                accQ[d] = fma2(pm34, wd[wb + 7], accQ[d]);
                accQ[d] = fma2(q45, wd[wb + 8], accQ[d]);
            }
            if (r >= 1 && r <= 30) {             // ky = 1 -> output row r-1
                const int d = (r - 1) % 3;
                accP[d] = fma2(q01, wd[wb + 3], accP[d]);
                accP[d] = fma2(pm12, wd[wb + 4], accP[d]);
                accP[d] = fma2(q23, wd[wb + 5], accP[d]);
                accQ[d] = fma2(q23, wd[wb + 3], accQ[d]);
                accQ[d] = fma2(pm34, wd[wb + 4], accQ[d]);
                accQ[d] = fma2(q45, wd[wb + 5], accQ[d]);
            }
            if (r <= 29) {                       // ky = 0 -> output row r
                const int d = r % 3;
                accP[d] = fma2(q01, wd[wb + 0], accP[d]);
                accP[d] = fma2(pm12, wd[wb + 1], accP[d]);
                accP[d] = fma2(q23, wd[wb + 2], accP[d]);
                accQ[d] = fma2(q23, wd[wb + 0], accQ[d]);
                accQ[d] = fma2(pm34, wd[wb + 1], accQ[d]);
                accQ[d] = fma2(q45, wd[wb + 2], accQ[d]);
            }
        }

        // output row y = r-2 complete: cols 4k..4k+3 of channel ch
        if (r >= 2) {
            const int y = r - 2;
            const int d = y % 3;
            const u64 tP = fma2(accP[d], sixth, halfc);   // packed v/6 + 0.5
            const u64 tQ = fma2(accQ[d], sixth, halfc);
            float v0, v1, v2, v3, t0, t1, t2, t3;
            upk2(accP[d], v0, v1); upk2(tP, t0, t1);
            upk2(accQ[d], v2, v3); upk2(tQ, t2, t3);
            float2 s0, s1;
            s0.x = hswish_relu(v0, t0); s0.y = hswish_relu(v1, t1);
            s1.x = hswish_relu(v2, t2); s1.y = hswish_relu(v3, t3);
            *reinterpret_cast<float2*>(outp + y * OW) = s0;          // cols 4k,4k+1
            if (k < 7)                                               // cols 30,31 masked
                *reinterpret_cast<float2*>(outp + y * OW + 2) = s1;  // cols 4k+2,4k+3
        }
    }
}

extern "C" void kernel_launch(void* const* d_in, const int* in_sizes, int n_in,
                              void* d_out, int out_size) {
    const float* x = (const float*)d_in[0];
    const float* w = (const float*)d_in[1];
    const float* b = (const float*)d_in[2];
    float* out = (float*)d_out;

    const int N = in_sizes[0] / (CIN * HH * WW);   // 4096
    conv3x3_hswish_kernel<<<N, 128>>>(x, w, b, out);
}

// round 15
// speedup vs baseline: 1.2945x; 1.2945x over previous
#include <cuda_runtime.h>
#include <cstdint>

#define CIN 3
#define COUT 16
#define HH 32
#define WW 32
#define OH 30
#define OW 30

typedef unsigned long long u64;

// ---- f32x2 packed-math helpers (SASS FFMA2 via PTX only) ----
__device__ __forceinline__ u64 pk2(float a, float b) {
    u64 r; asm("mov.b64 %0, {%1, %2};" : "=l"(r) : "f"(a), "f"(b)); return r;
}
__device__ __forceinline__ u64 dup2(float a) {
    u64 r; asm("mov.b64 %0, {%1, %1};" : "=l"(r) : "f"(a)); return r;
}
__device__ __forceinline__ u64 fma2(u64 a, u64 b, u64 c) {
    u64 d; asm("fma.rn.f32x2 %0, %1, %2, %3;" : "=l"(d) : "l"(a), "l"(b), "l"(c)); return d;
}
__device__ __forceinline__ void upk2(u64 v, float& a, float& b) {
    asm("mov.b64 {%0, %1}, %2;" : "=f"(a), "=f"(b) : "l"(v));
}
// activation tail: relu(v)*min(v+3,6)/6 == max(v,0)*min(t,1), t = v/6+0.5
__device__ __forceinline__ float hswish_relu(float v, float t) {
    return fmaxf(v, 0.0f) * fminf(t, 1.0f);
}

// Direct conv v8b = R11 (best: 80.6us, 96 regs, 5 blocks/SM) with a slimmer
// per-row epilogue: t = v/6+0.5 computed PACKED (one fma2 replaces two scalar
// FMAs) and bias folded into the first tap (no per-row acc init MOV).
// (max/min/mul.f32x2 do NOT exist on sm_103 — R14 compile fail — so the
// max/min/mul tail stays scalar.)
// Grid 8192: block b -> image b>>1, channel-half b&1. 128 threads = 4 warps;
// warp -> channel pair; lane = output column (30 active). Streaming over
// input rows r (feeds output rows r/r-1/r-2 at ky 0/1/2), scalar LDS.32
// prefetch one full row ahead into parity buffers. Fully unrolled.
__global__ void __launch_bounds__(128, 5) conv3x3_hswish_kernel(
    const float* __restrict__ x,
    const float* __restrict__ wgt,
    const float* __restrict__ bias,
    float* __restrict__ out)
{
    __shared__ float s_in[CIN * HH * WW];   // 12 KB

    const int n    = blockIdx.x >> 1;
    const int half = blockIdx.x & 1;
    const int tid  = threadIdx.x;

    {   // coalesced image load: 768 float4 / 128 threads = 6 each
        const float4* src = reinterpret_cast<const float4*>(x + (size_t)n * (CIN * HH * WW));
        float4* dst = reinterpret_cast<float4*>(s_in);
        #pragma unroll
        for (int i = 0; i < 6; i++) dst[tid + i * 128] = src[tid + i * 128];
    }
    __syncthreads();

    const int warp = tid >> 5;
    const int lane = tid & 31;
    const int c0   = (half * 4 + warp) * 2;   // channel pair

    // packed weights: wp[ci*9 + ky*3 + kx] = {w[c0], w[c0+1]}
    u64 wp[27];
    #pragma unroll
    for (int t = 0; t < 27; t++)
        wp[t] = pk2(wgt[c0 * 27 + t], wgt[(c0 + 1) * 27 + t]);
    const u64 bp = pk2(bias[c0], bias[c0 + 1]);

    // packed activation constants (t = v * 1/6 + 0.5, one fma2)
    const u64 sixth = dup2(1.0f / 6.0f);
    const u64 halfc = dup2(0.5f);

    if (lane >= OW) return;   // barrier done; lanes 30/31 retire

    const float* base = s_in + lane;   // [ci*1024 + row*32 + kx]
    float* out0 = out + ((size_t)n * COUT + c0) * (OH * OW) + lane;

    // scalar double-buffered row window; parity compile-time (full unroll).
    float nb0[9], nb1[9];
    u64 acc[3];               // acc[y % 3] = accumulator for output row y

    #pragma unroll
    for (int ci = 0; ci < CIN; ci++)
        #pragma unroll
        for (int kx = 0; kx < 3; kx++)
            nb0[ci * 3 + kx] = base[ci * 1024 + kx];   // input row 0

    #pragma unroll
    for (int r = 0; r < 32; r++) {
        // prefetch input row r+1 into the other buffer (full-row distance)
        if (r < 31) {
            #pragma unroll
            for (int ci = 0; ci < CIN; ci++)
                #pragma unroll
                for (int kx = 0; kx < 3; kx++) {
                    float v = base[ci * 1024 + (r + 1) * 32 + kx];
                    if (r & 1) nb0[ci * 3 + kx] = v; else nb1[ci * 3 + kx] = v;
                }
        }

        #pragma unroll
        for (int t = 0; t < 9; t++) {
            const int ci = t / 3, kx = t % 3;
            const u64 dv = dup2((r & 1) ? nb1[t] : nb0[t]);  // one dup, 3 uses
            if (r >= 2)
                acc[(r - 2) % 3] = fma2(dv, wp[ci * 9 + 6 + kx], acc[(r - 2) % 3]);
            if (r >= 1 && r <= 30)
                acc[(r - 1) % 3] = fma2(dv, wp[ci * 9 + 3 + kx], acc[(r - 1) % 3]);
            if (r <= 29) {
                // bias folded into the first tap of each output row
                acc[r % 3] = (t == 0) ? fma2(dv, wp[0], bp)
                                      : fma2(dv, wp[ci * 9 + 0 + kx], acc[r % 3]);
            }
        }

        // output row y = r-2 complete: packed t, scalar max/min/mul tail
        if (r >= 2) {
            const u64 v = acc[(r - 2) % 3];
            const u64 t = fma2(v, sixth, halfc);           // {v0,v1}/6 + 0.5
            float v0, v1, t0, t1;
            upk2(v, v0, v1);
            upk2(t, t0, t1);
            const int yoff = (r - 2) * OW;
            out0[yoff]           = hswish_relu(v0, t0);
            out0[OH * OW + yoff] = hswish_relu(v1, t1);
        }
    }
}

extern "C" void kernel_launch(void* const* d_in, const int* in_sizes, int n_in,
                              void* d_out, int out_size) {
    const float* x = (const float*)d_in[0];
    const float* w = (const float*)d_in[1];
    const float* b = (const float*)d_in[2];
    float* out = (float*)d_out;

    const int N = in_sizes[0] / (CIN * HH * WW);   // 4096
    conv3x3_hswish_kernel<<<N * 2, 128>>>(x, w, b, out);
}